// round 8
// baseline (speedup 1.0000x reference)
#include <cuda_runtime.h>
#include <math.h>
#include <float.h>

#define BATCH 8
#define NPTS  4096
#define KN    10
#define NNB   9
#define NBIN  256
#define PI_F  3.14159265358979323846f
#define INF_F __int_as_float(0x7f800000)

// scratch
__device__ int    g_knn_idx[BATCH * NPTS * NNB];
__device__ float4 g_sorted[BATCH * NPTS];        // bin-sorted: {x,y,z, 0.5|p|^2}
__device__ int    g_sidx[BATCH * NPTS];          // sorted rank -> original idx
__device__ int    g_bins[BATCH][NBIN + 1];       // bin start offsets
__device__ float  g_zmin[BATCH], g_wbin[BATCH], g_invw[BATCH];

// ---------------------------------------------------------------------------
// insert: unsorted top-10, replace (first) slot equal to running max.
// parallel prefix-OR first-match + FMNMX tree. (proven exact, rounds 3-7)
// ---------------------------------------------------------------------------
#define KNN_INSERT(e, c)                                                     \
    if ((e) < mx) {                                                          \
        bool m0 = (bd[0] == mx), m1 = (bd[1] == mx);                         \
        bool m2 = (bd[2] == mx), m3 = (bd[3] == mx);                         \
        bool m4 = (bd[4] == mx), m5 = (bd[5] == mx);                         \
        bool m6 = (bd[6] == mx), m7 = (bd[7] == mx);                         \
        bool m8 = (bd[8] == mx), m9 = (bd[9] == mx);                         \
        bool o01 = m0 | m1, o23 = m2 | m3, o45 = m4 | m5, o67 = m6 | m7;     \
        bool o03 = o01 | o23, o07 = o03 | o45 | o67;                         \
        if (m0)                      { bd[0] = (e); bi[0] = (c); }           \
        if (m1 & !m0)                { bd[1] = (e); bi[1] = (c); }           \
        if (m2 & !o01)               { bd[2] = (e); bi[2] = (c); }           \
        if (m3 & !(o01 | m2))        { bd[3] = (e); bi[3] = (c); }           \
        if (m4 & !o03)               { bd[4] = (e); bi[4] = (c); }           \
        if (m5 & !(o03 | m4))        { bd[5] = (e); bi[5] = (c); }           \
        if (m6 & !(o03 | o45))       { bd[6] = (e); bi[6] = (c); }           \
        if (m7 & !(o03 | o45 | m6))  { bd[7] = (e); bi[7] = (c); }           \
        if (m8 & !o07)               { bd[8] = (e); bi[8] = (c); }           \
        if (m9 & !(o07 | m8))        { bd[9] = (e); bi[9] = (c); }           \
        float x0 = fmaxf(bd[0], bd[1]);                                      \
        float x1 = fmaxf(bd[2], bd[3]);                                      \
        float x2 = fmaxf(bd[4], bd[5]);                                      \
        float x3 = fmaxf(bd[6], bd[7]);                                      \
        float x4 = fmaxf(bd[8], bd[9]);                                      \
        mx = fmaxf(fmaxf(fmaxf(x0, x1), fmaxf(x2, x3)), x4);                 \
    }

// ---------------------------------------------------------------------------
// Kernel A: counting sort by z into NBIN bins. One block per batch.
// ---------------------------------------------------------------------------
__global__ void __launch_bounds__(512) binsort_kernel(const float* __restrict__ x)
{
    __shared__ float sred[512];
    __shared__ int   cnt[NBIN];
    __shared__ int   offs[NBIN];
    __shared__ float sinfo[3];    // zmin, w, invw

    const int b   = blockIdx.x;
    const int tid = threadIdx.x;
    const float* xb = x + b * 3 * NPTS;
    const float* zb = xb + 2 * NPTS;

    // --- z min/max reduction ---
    float lmin = INF_F, lmax = -INF_F;
    for (int i = tid; i < NPTS; i += 512) {
        float z = zb[i];
        lmin = fminf(lmin, z);
        lmax = fmaxf(lmax, z);
    }
    sred[tid] = lmin;
    __syncthreads();
    for (int s = 256; s > 0; s >>= 1) {
        if (tid < s) sred[tid] = fminf(sred[tid], sred[tid + s]);
        __syncthreads();
    }
    float zmin = sred[0];
    __syncthreads();
    sred[tid] = lmax;
    __syncthreads();
    for (int s = 256; s > 0; s >>= 1) {
        if (tid < s) sred[tid] = fmaxf(sred[tid], sred[tid + s]);
        __syncthreads();
    }
    float zmax = sred[0];
    __syncthreads();

    if (tid == 0) {
        float w = fmaxf((zmax - zmin) * (1.0f / NBIN) * (1.0f + 1e-6f), 1e-30f);
        sinfo[0] = zmin; sinfo[1] = w; sinfo[2] = 1.0f / w;
        g_zmin[b] = zmin; g_wbin[b] = w; g_invw[b] = 1.0f / w;
    }
    if (tid < NBIN) cnt[tid] = 0;
    __syncthreads();

    const float izm = sinfo[0], iinv = sinfo[2];

    // --- histogram ---
    for (int i = tid; i < NPTS; i += 512) {
        int bin = min(NBIN - 1, (int)((zb[i] - izm) * iinv));
        atomicAdd(&cnt[bin], 1);
    }
    __syncthreads();

    // --- inclusive Kogge-Stone scan over NBIN ---
    if (tid < NBIN) offs[tid] = cnt[tid];
    __syncthreads();
    for (int d = 1; d < NBIN; d <<= 1) {
        int v = 0;
        if (tid < NBIN && tid >= d) v = offs[tid - d];
        __syncthreads();
        if (tid < NBIN && tid >= d) offs[tid] += v;
        __syncthreads();
    }

    // exclusive starts -> global + reset cnt as scatter cursor
    int excl = 0;
    if (tid < NBIN) {
        excl = offs[tid] - cnt[tid];
        g_bins[b][tid] = excl;
    }
    if (tid == 0) g_bins[b][NBIN] = NPTS;
    __syncthreads();
    if (tid < NBIN) cnt[tid] = excl;
    __syncthreads();

    // --- scatter ---
    for (int i = tid; i < NPTS; i += 512) {
        float px = xb[i], py = xb[NPTS + i], pz = zb[i];
        int bin = min(NBIN - 1, (int)((pz - izm) * iinv));
        int pos = atomicAdd(&cnt[bin], 1);
        g_sorted[b * NPTS + pos] =
            make_float4(px, py, pz, 0.5f * (px * px + py * py + pz * pz));
        g_sidx[b * NPTS + pos] = i;
    }
}

// ---------------------------------------------------------------------------
// Kernel B: exact kNN via outward bin walk with edge-bound termination.
// 1 thread per query (sorted order). d >= dz^2 => e >= 0.5 dz^2 - 0.5|q|^2.
// ---------------------------------------------------------------------------
__global__ void __launch_bounds__(256) knn_kernel()
{
    extern __shared__ char dsm[];
    float4* spt  = (float4*)dsm;                       // 64 KB
    int*    sidx = (int*)(dsm + NPTS * 16);            // 16 KB
    int*    sbin = (int*)(dsm + NPTS * 16 + NPTS * 4); // 1028 B

    const int b  = blockIdx.x >> 4;           // 16 blocks per batch
    const int q0 = (blockIdx.x & 15) << 8;    // 256 queries (sorted ranks)
    const int tid = threadIdx.x;

    const float4* gb = g_sorted + b * NPTS;
    const int*    gi = g_sidx   + b * NPTS;
    for (int i = tid; i < NPTS; i += 256) {
        spt[i]  = gb[i];
        sidx[i] = gi[i];
    }
    for (int i = tid; i < NBIN + 1; i += 256) sbin[i] = g_bins[b][i];
    __syncthreads();

    const float zmin = g_zmin[b];
    const float w    = g_wbin[b];
    const float invw = g_invw[b];

    const int r = q0 + tid;
    const float4 qp = spt[r];
    const float qz = qp.z;
    const float nqx = -qp.x, nqy = -qp.y, nqz = -qp.z;

    float bd[KN];
    int   bi[KN];
#pragma unroll
    for (int s = 0; s < KN; ++s) { bd[s] = INF_F; bi[s] = 0; }
    float mx = INF_F;

    const int mybin = min(NBIN - 1, (int)((qz - zmin) * invw));

    // evaluate own bin
    {
        int cs = sbin[mybin], ce = sbin[mybin + 1];
#pragma unroll 2
        for (int c = cs; c < ce; ++c) {
            float4 p = spt[c];
            float e = fmaf(nqx, p.x, fmaf(nqy, p.y, fmaf(nqz, p.z, p.w)));
            KNN_INSERT(e, c);
        }
    }

    int jlo = mybin, jhi = mybin;
    float dzlo = (jlo > 0)        ? fmaxf(qz - (zmin + jlo * w), 0.0f)        : INF_F;
    float dzhi = (jhi < NBIN - 1) ? fmaxf((zmin + (jhi + 1) * w) - qz, 0.0f)  : INF_F;

#pragma unroll 1
    while (true) {
        bool useLo = (dzlo <= dzhi);
        float dz = useLo ? dzlo : dzhi;
        float bound = fmaf(0.5f * dz, dz, -qp.w);
        if (bound > mx + 1e-5f) break;   // min side pruned => both pruned

        int j;
        if (useLo) { --jlo; j = jlo; }
        else       { ++jhi; j = jhi; }

        int cs = sbin[j], ce = sbin[j + 1];
#pragma unroll 2
        for (int c = cs; c < ce; ++c) {
            float4 p = spt[c];
            float e = fmaf(nqx, p.x, fmaf(nqy, p.y, fmaf(nqz, p.z, p.w)));
            KNN_INSERT(e, c);
        }

        if (useLo) dzlo = (jlo > 0)        ? fmaxf(qz - (zmin + jlo * w), 0.0f)       : INF_F;
        else       dzhi = (jhi < NBIN - 1) ? fmaxf((zmin + (jhi + 1) * w) - qz, 0.0f) : INF_F;
    }

    // self = strict global min; emit the other 9 mapped to original indices
    float mn = bd[0]; int ms = 0;
#pragma unroll
    for (int s = 1; s < KN; ++s) {
        if (bd[s] < mn) { mn = bd[s]; ms = s; }
    }
    const int oq = sidx[r];
    int* outp = g_knn_idx + (b * NPTS + oq) * NNB;
    int k = 0;
#pragma unroll
    for (int s = 0; s < KN; ++s) {
        if (s != ms) { outp[k] = sidx[bi[s]]; ++k; }
    }
}

// ---------------------------------------------------------------------------
// Kernel 2: umbrella features + fused MLP (BN folded). One thread per (b,n).
// ---------------------------------------------------------------------------
__global__ void __launch_bounds__(256) feat_kernel(
    const float* __restrict__ x,
    const float* __restrict__ conv1_w,
    const float* __restrict__ bn1_g, const float* __restrict__ bn1_b,
    const float* __restrict__ bn1_m, const float* __restrict__ bn1_v,
    const float* __restrict__ conv2_w, const float* __restrict__ conv2_b,
    const float* __restrict__ bn2_g, const float* __restrict__ bn2_b,
    const float* __restrict__ bn2_m, const float* __restrict__ bn2_v,
    const float* __restrict__ conv3_w, const float* __restrict__ conv3_b,
    float* __restrict__ out)
{
    extern __shared__ float4 spts[];
    __shared__ float W1f[81], W2f[81], W3s[81];
    __shared__ float b1f[9], b2f[9], b3f[9];

    const int b  = blockIdx.x >> 4;
    const int n0 = (blockIdx.x & 15) * 256;
    const int tid = threadIdx.x;

    if (tid < 81) {
        int o = tid / 9;
        float i1 = bn1_g[o] * rsqrtf(bn1_v[o] + 1e-5f);
        float i2 = bn2_g[o] * rsqrtf(bn2_v[o] + 1e-5f);
        W1f[tid] = conv1_w[tid] * i1;
        W2f[tid] = conv2_w[tid] * i2;
        W3s[tid] = conv3_w[tid];
        if (tid < 9) {
            float j1 = bn1_g[tid] * rsqrtf(bn1_v[tid] + 1e-5f);
            float j2 = bn2_g[tid] * rsqrtf(bn2_v[tid] + 1e-5f);
            b1f[tid] = bn1_b[tid] - bn1_m[tid] * j1;
            b2f[tid] = conv2_b[tid] * j2 + bn2_b[tid] - bn2_m[tid] * j2;
            b3f[tid] = conv3_b[tid];
        }
    }

    const float* xb = x + b * 3 * NPTS;
    for (int i = tid; i < NPTS; i += blockDim.x) {
        spts[i] = make_float4(xb[i], xb[NPTS + i], xb[2 * NPTS + i], 0.0f);
    }
    __syncthreads();

    const int n = n0 + tid;
    float4 p = spts[n];

    float gx[NNB], gy[NNB], gz[NNB], ph[NNB];
    const int* nb = g_knn_idx + (b * NPTS + n) * NNB;
#pragma unroll
    for (int j = 0; j < NNB; ++j) {
        float4 pp = spts[nb[j]];
        gx[j] = pp.x - p.x;
        gy[j] = pp.y - p.y;
        gz[j] = pp.z - p.z;
        ph[j] = atan2f(gy[j], gx[j]);
    }

#pragma unroll 1
    for (int a = 1; a < NNB; ++a) {
        float kp = ph[a], kx = gx[a], ky = gy[a], kz = gz[a];
        int t = a - 1;
        while (t >= 0 && ph[t] > kp) {
            ph[t + 1] = ph[t]; gx[t + 1] = gx[t]; gy[t + 1] = gy[t]; gz[t + 1] = gz[t];
            --t;
        }
        ph[t + 1] = kp; gx[t + 1] = kx; gy[t + 1] = ky; gz[t + 1] = kz;
    }

    float acc[9];
#pragma unroll
    for (int o = 0; o < 9; ++o) acc[o] = 0.0f;

    float pos = 1.0f;

#pragma unroll 1
    for (int j = 0; j < NNB; ++j) {
        int jn = (j + 1 == NNB) ? 0 : j + 1;
        float sx = gx[j],  sy = gy[j],  sz = gz[j];
        float rx = gx[jn], ry = gy[jn], rz = gz[jn];

        float cxv = sy * rz - sz * ry;
        float cyv = sz * rx - sx * rz;
        float czv = sx * ry - sy * rx;
        float nrm = sqrtf(cxv * cxv + cyv * cyv + czv * czv);
        float inn = 1.0f / fmaxf(nrm, 1e-10f);
        float ux = cxv * inn, uy = cyv * inn, uz = czv * inn;
        if (j == 0) pos = (ux > 0.0f) ? 1.0f : -1.0f;
        float nx = ux * pos, ny = uy * pos, nz = uz * pos;
        nx = isnan(nx) ? 0.0f : nx;
        ny = isnan(ny) ? 0.0f : ny;
        nz = isnan(nz) ? 0.0f : nz;

        float ccx = (sx + rx) * (1.0f / 3.0f);
        float ccy = (sy + ry) * (1.0f / 3.0f);
        float ccz = (sz + rz) * (1.0f / 3.0f);
        float rho = sqrtf(ccx * ccx + ccy * ccy + ccz * ccz);
        float ct  = ccz / fmaxf(rho, 1e-8f);
        ct = fminf(fmaxf(ct, -1.0f), 1.0f);
        float th  = acosf(ct) * (1.0f / PI_F);
        float phc = atan2f(ccy, ccx) * (1.0f / (2.0f * PI_F)) + 0.5f;

        float f[9] = { ccx, ccy, ccz, rho, th, phc, nx, ny, nz };

        float h1v[9];
#pragma unroll
        for (int o = 0; o < 9; ++o) {
            float a = b1f[o];
#pragma unroll
            for (int c = 0; c < 9; ++c) a = fmaf(W1f[o * 9 + c], f[c], a);
            h1v[o] = fmaxf(a, 0.0f);
        }
        float h2v[9];
#pragma unroll
        for (int o = 0; o < 9; ++o) {
            float a = b2f[o];
#pragma unroll
            for (int c = 0; c < 9; ++c) a = fmaf(W2f[o * 9 + c], h1v[c], a);
            h2v[o] = fmaxf(a, 0.0f);
        }
#pragma unroll
        for (int o = 0; o < 9; ++o) {
            float a = b3f[o];
#pragma unroll
            for (int c = 0; c < 9; ++c) a = fmaf(W3s[o * 9 + c], h2v[c], a);
            acc[o] += a;
        }
    }

    float* ob = out + b * 9 * NPTS + n;
#pragma unroll
    for (int o = 0; o < 9; ++o) ob[o * NPTS] = acc[o];
}

// ---------------------------------------------------------------------------
extern "C" void kernel_launch(void* const* d_in, const int* in_sizes, int n_in,
                              void* d_out, int out_size)
{
    const float* x       = (const float*)d_in[0];
    const float* conv1_w = (const float*)d_in[1];
    const float* bn1_g   = (const float*)d_in[2];
    const float* bn1_b   = (const float*)d_in[3];
    const float* bn1_m   = (const float*)d_in[4];
    const float* bn1_v   = (const float*)d_in[5];
    const float* conv2_w = (const float*)d_in[6];
    const float* conv2_b = (const float*)d_in[7];
    const float* bn2_g   = (const float*)d_in[8];
    const float* bn2_b   = (const float*)d_in[9];
    const float* bn2_m   = (const float*)d_in[10];
    const float* bn2_v   = (const float*)d_in[11];
    const float* conv3_w = (const float*)d_in[12];
    const float* conv3_b = (const float*)d_in[13];
    float* out = (float*)d_out;

    const int smem_knn  = NPTS * 16 + NPTS * 4 + (NBIN + 1) * 4;  // ~81 KB
    const int smem_feat = NPTS * (int)sizeof(float4);             // 64 KB
    cudaFuncSetAttribute(knn_kernel,  cudaFuncAttributeMaxDynamicSharedMemorySize, smem_knn);
    cudaFuncSetAttribute(feat_kernel, cudaFuncAttributeMaxDynamicSharedMemorySize, smem_feat);

    binsort_kernel<<<BATCH, 512>>>(x);
    knn_kernel<<<BATCH * (NPTS / 256), 256, smem_knn>>>();
    feat_kernel<<<BATCH * (NPTS / 256), 256, smem_feat>>>(
        x, conv1_w, bn1_g, bn1_b, bn1_m, bn1_v,
        conv2_w, conv2_b, bn2_g, bn2_b, bn2_m, bn2_v,
        conv3_w, conv3_b, out);
}

// round 9
// speedup vs baseline: 1.1311x; 1.1311x over previous
#include <cuda_runtime.h>
#include <math.h>
#include <float.h>

#define BATCH 8
#define NPTS  4096
#define KN    10
#define NNB   9
#define NBIN  256
#define PI_F  3.14159265358979323846f
#define INF_F __int_as_float(0x7f800000)

// scratch
__device__ int    g_knn_idx[BATCH * NPTS * NNB];
__device__ float4 g_sorted[BATCH * NPTS];        // bin-sorted: {x,y,z, 0.5|p|^2}
__device__ int    g_sidx[BATCH * NPTS];          // sorted rank -> original idx
__device__ int    g_bins[BATCH][NBIN + 1];       // bin start offsets
__device__ float  g_zmin[BATCH], g_wbin[BATCH], g_invw[BATCH];

// ---------------------------------------------------------------------------
// insert: unsorted top-10, replace (first) slot equal to running max.
// parallel prefix-OR first-match + FMNMX tree. (proven exact, rounds 3-8)
// ---------------------------------------------------------------------------
#define KNN_INSERT_CORE(e, c)                                                \
    {                                                                        \
        bool m0 = (bd[0] == mx), m1 = (bd[1] == mx);                         \
        bool m2 = (bd[2] == mx), m3 = (bd[3] == mx);                         \
        bool m4 = (bd[4] == mx), m5 = (bd[5] == mx);                         \
        bool m6 = (bd[6] == mx), m7 = (bd[7] == mx);                         \
        bool m8 = (bd[8] == mx), m9 = (bd[9] == mx);                         \
        bool o01 = m0 | m1, o23 = m2 | m3, o45 = m4 | m5, o67 = m6 | m7;     \
        bool o03 = o01 | o23, o07 = o03 | o45 | o67;                         \
        if (m0)                      { bd[0] = (e); bi[0] = (c); }           \
        if (m1 & !m0)                { bd[1] = (e); bi[1] = (c); }           \
        if (m2 & !o01)               { bd[2] = (e); bi[2] = (c); }           \
        if (m3 & !(o01 | m2))        { bd[3] = (e); bi[3] = (c); }           \
        if (m4 & !o03)               { bd[4] = (e); bi[4] = (c); }           \
        if (m5 & !(o03 | m4))        { bd[5] = (e); bi[5] = (c); }           \
        if (m6 & !(o03 | o45))       { bd[6] = (e); bi[6] = (c); }           \
        if (m7 & !(o03 | o45 | m6))  { bd[7] = (e); bi[7] = (c); }           \
        if (m8 & !o07)               { bd[8] = (e); bi[8] = (c); }           \
        if (m9 & !(o07 | m8))        { bd[9] = (e); bi[9] = (c); }           \
        float x0 = fmaxf(bd[0], bd[1]);                                      \
        float x1 = fmaxf(bd[2], bd[3]);                                      \
        float x2 = fmaxf(bd[4], bd[5]);                                      \
        float x3 = fmaxf(bd[6], bd[7]);                                      \
        float x4 = fmaxf(bd[8], bd[9]);                                      \
        mx = fmaxf(fmaxf(fmaxf(x0, x1), fmaxf(x2, x3)), x4);                 \
    }

#define KNN_INSERT(e, c) if ((e) < mx) KNN_INSERT_CORE(e, c)

// ---------------------------------------------------------------------------
// Kernel A: counting sort by z into NBIN bins. One block per batch.
// ---------------------------------------------------------------------------
__global__ void __launch_bounds__(512) binsort_kernel(const float* __restrict__ x)
{
    __shared__ float sred[512];
    __shared__ int   cnt[NBIN];
    __shared__ int   offs[NBIN];
    __shared__ float sinfo[3];

    const int b   = blockIdx.x;
    const int tid = threadIdx.x;
    const float* xb = x + b * 3 * NPTS;
    const float* zb = xb + 2 * NPTS;

    float lmin = INF_F, lmax = -INF_F;
    for (int i = tid; i < NPTS; i += 512) {
        float z = zb[i];
        lmin = fminf(lmin, z);
        lmax = fmaxf(lmax, z);
    }
    sred[tid] = lmin;
    __syncthreads();
    for (int s = 256; s > 0; s >>= 1) {
        if (tid < s) sred[tid] = fminf(sred[tid], sred[tid + s]);
        __syncthreads();
    }
    float zmin = sred[0];
    __syncthreads();
    sred[tid] = lmax;
    __syncthreads();
    for (int s = 256; s > 0; s >>= 1) {
        if (tid < s) sred[tid] = fmaxf(sred[tid], sred[tid + s]);
        __syncthreads();
    }
    float zmax = sred[0];
    __syncthreads();

    if (tid == 0) {
        float w = fmaxf((zmax - zmin) * (1.0f / NBIN) * (1.0f + 1e-6f), 1e-30f);
        sinfo[0] = zmin; sinfo[2] = 1.0f / w;
        g_zmin[b] = zmin; g_wbin[b] = w; g_invw[b] = 1.0f / w;
    }
    if (tid < NBIN) cnt[tid] = 0;
    __syncthreads();

    const float izm = sinfo[0], iinv = sinfo[2];

    for (int i = tid; i < NPTS; i += 512) {
        int bin = min(NBIN - 1, (int)((zb[i] - izm) * iinv));
        atomicAdd(&cnt[bin], 1);
    }
    __syncthreads();

    if (tid < NBIN) offs[tid] = cnt[tid];
    __syncthreads();
    for (int d = 1; d < NBIN; d <<= 1) {
        int v = 0;
        if (tid < NBIN && tid >= d) v = offs[tid - d];
        __syncthreads();
        if (tid < NBIN && tid >= d) offs[tid] += v;
        __syncthreads();
    }

    int excl = 0;
    if (tid < NBIN) {
        excl = offs[tid] - cnt[tid];
        g_bins[b][tid] = excl;
    }
    if (tid == 0) g_bins[b][NBIN] = NPTS;
    __syncthreads();
    if (tid < NBIN) cnt[tid] = excl;
    __syncthreads();

    for (int i = tid; i < NPTS; i += 512) {
        float px = xb[i], py = xb[NPTS + i], pz = zb[i];
        int bin = min(NBIN - 1, (int)((pz - izm) * iinv));
        int pos = atomicAdd(&cnt[bin], 1);
        g_sorted[b * NPTS + pos] =
            make_float4(px, py, pz, 0.5f * (px * px + py * py + pz * pz));
        g_sidx[b * NPTS + pos] = i;
    }
}

// ---------------------------------------------------------------------------
// Kernel B: kNN. Block owns 256 consecutive sorted ranks; all threads scan
// one block-uniform bin-aligned window (warp-coherent, broadcast LDS),
// 2 threads per query (half-window each), argmin fast-path group insert.
// Exact 2-way merge; per-query exact bin-walk fallback past the window.
// ---------------------------------------------------------------------------
__global__ void __launch_bounds__(512) knn_kernel()
{
    extern __shared__ char dsm[];
    float4* spt  = (float4*)dsm;                          // 64 KB
    int*    sidx = (int*)(dsm + 65536);                   // 16 KB
    int*    sbin = (int*)(dsm + 65536 + 16384);           // 1028 B
    float*  pd   = (float*)(dsm + 82948 + 16);            // 20 KB
    int*    pi   = (int*)(dsm + 82948 + 16 + 20480);      // 20 KB

    const int b  = blockIdx.x >> 4;           // 16 blocks per batch
    const int q0 = (blockIdx.x & 15) << 8;    // 256 queries (sorted ranks)
    const int tid = threadIdx.x;

    const float4* gb = g_sorted + b * NPTS;
    const int*    gi = g_sidx   + b * NPTS;
    for (int i = tid; i < NPTS; i += 512) {
        spt[i]  = gb[i];
        sidx[i] = gi[i];
    }
    for (int i = tid; i < NBIN + 1; i += 512) sbin[i] = g_bins[b][i];
    __syncthreads();

    const float zmin = g_zmin[b];
    const float w    = g_wbin[b];

    // block-uniform window: bins covering ranks [q0-384, q0+640)
    int jlo, jhi;
    {
        int tlo = max(q0 - 384, 0);
        int thi = min(q0 + 639, NPTS - 1);
        int lo = 0, hi = NBIN - 1;
        while (lo < hi) { int m = (lo + hi + 1) >> 1; if (sbin[m] <= tlo) lo = m; else hi = m - 1; }
        jlo = lo;
        lo = 0; hi = NBIN - 1;
        while (lo < hi) { int m = (lo + hi + 1) >> 1; if (sbin[m] <= thi) lo = m; else hi = m - 1; }
        jhi = lo;
    }
    const int wstart = sbin[jlo];
    const int wend   = sbin[jhi + 1];
    const int wmid   = (wstart + wend) >> 1;

    const int sub = tid >> 8;        // warps 0-7: sub 0, warps 8-15: sub 1
    const int ql  = tid & 255;
    const int r   = q0 + ql;

    const float4 qp = spt[r];
    const float qz  = qp.z;
    const float nqx = -qp.x, nqy = -qp.y, nqz = -qp.z;

    float bd[KN];
    int   bi[KN];
#pragma unroll
    for (int s = 0; s < KN; ++s) { bd[s] = INF_F; bi[s] = 0; }
    float mx = INF_F;

    const int cs = sub ? wmid : wstart;
    const int ce = sub ? wend : wmid;

    int c = cs;
#pragma unroll 2
    for (; c + 3 < ce; c += 4) {
        float4 p0 = spt[c];
        float4 p1 = spt[c + 1];
        float4 p2 = spt[c + 2];
        float4 p3 = spt[c + 3];
        float e0 = fmaf(nqx, p0.x, fmaf(nqy, p0.y, fmaf(nqz, p0.z, p0.w)));
        float e1 = fmaf(nqx, p1.x, fmaf(nqy, p1.y, fmaf(nqz, p1.z, p1.w)));
        float e2 = fmaf(nqx, p2.x, fmaf(nqy, p2.y, fmaf(nqz, p2.z, p2.w)));
        float e3 = fmaf(nqx, p3.x, fmaf(nqy, p3.y, fmaf(nqz, p3.z, p3.w)));
        float m01 = fminf(e0, e1);
        float m23 = fminf(e2, e3);
        float em  = fminf(m01, m23);
        if (em < mx) {
            bool a01 = (e0 <= e1);
            bool a23 = (e2 <= e3);
            bool a   = (m01 <= m23);
            int  i01 = a01 ? c     : c + 1;
            int  i23 = a23 ? c + 2 : c + 3;
            int  cm  = a ? i01 : i23;
            KNN_INSERT_CORE(em, cm);
            bool k0 = a & a01, k1 = a & !a01, k2 = !a & a23, k3 = !a & !a23;
            e0 = k0 ? INF_F : e0;
            e1 = k1 ? INF_F : e1;
            e2 = k2 ? INF_F : e2;
            e3 = k3 ? INF_F : e3;
            float em2 = fminf(fminf(e0, e1), fminf(e2, e3));
            if (em2 < mx) {
                KNN_INSERT(e0, c);
                KNN_INSERT(e1, c + 1);
                KNN_INSERT(e2, c + 2);
                KNN_INSERT(e3, c + 3);
            }
        }
    }
    for (; c < ce; ++c) {
        float4 p = spt[c];
        float e = fmaf(nqx, p.x, fmaf(nqy, p.y, fmaf(nqz, p.z, p.w)));
        KNN_INSERT(e, c);
    }

    // --- exact merge of the two partial lists ---
    __syncthreads();
    const int base = (ql * 2 + sub) * KN;
#pragma unroll
    for (int s = 0; s < KN; ++s) { pd[base + s] = bd[s]; pi[base + s] = bi[s]; }
    __syncthreads();

    if (sub == 0) {
        const int ob = (ql * 2 + 1) * KN;
#pragma unroll
        for (int s = 0; s < KN; ++s) {
            float e = pd[ob + s];
            int   cc = pi[ob + s];
            KNN_INSERT(e, cc);
        }

        // --- exact fallback: bin-walk beyond the window (rare) ---
        int flo = jlo, fhi = jhi;
        float dzlo = (flo > 0)        ? fmaxf(qz - (zmin + flo * w), 0.0f)       : INF_F;
        float dzhi = (fhi < NBIN - 1) ? fmaxf((zmin + (fhi + 1) * w) - qz, 0.0f) : INF_F;
#pragma unroll 1
        while (true) {
            bool useLo = (dzlo <= dzhi);
            float dz = useLo ? dzlo : dzhi;
            float bound = fmaf(0.5f * dz, dz, -qp.w);
            if (bound > mx + 1e-5f) break;

            int j;
            if (useLo) { --flo; j = flo; }
            else       { ++fhi; j = fhi; }

            int fs = sbin[j], fe = sbin[j + 1];
            for (int cc = fs; cc < fe; ++cc) {
                float4 p = spt[cc];
                float e = fmaf(nqx, p.x, fmaf(nqy, p.y, fmaf(nqz, p.z, p.w)));
                KNN_INSERT(e, cc);
            }

            if (useLo) dzlo = (flo > 0)        ? fmaxf(qz - (zmin + flo * w), 0.0f)       : INF_F;
            else       dzhi = (fhi < NBIN - 1) ? fmaxf((zmin + (fhi + 1) * w) - qz, 0.0f) : INF_F;
        }

        // self = strict global min; emit the other 9 mapped to original ids
        float mn = bd[0]; int ms = 0;
#pragma unroll
        for (int s = 1; s < KN; ++s) {
            if (bd[s] < mn) { mn = bd[s]; ms = s; }
        }
        const int oq = sidx[r];
        int* outp = g_knn_idx + (b * NPTS + oq) * NNB;
        int k = 0;
#pragma unroll
        for (int s = 0; s < KN; ++s) {
            if (s != ms) { outp[k] = sidx[bi[s]]; ++k; }
        }
    }
}

// ---------------------------------------------------------------------------
// Kernel 2: umbrella features + fused MLP (BN folded). One thread per (b,n).
// ---------------------------------------------------------------------------
__global__ void __launch_bounds__(256) feat_kernel(
    const float* __restrict__ x,
    const float* __restrict__ conv1_w,
    const float* __restrict__ bn1_g, const float* __restrict__ bn1_b,
    const float* __restrict__ bn1_m, const float* __restrict__ bn1_v,
    const float* __restrict__ conv2_w, const float* __restrict__ conv2_b,
    const float* __restrict__ bn2_g, const float* __restrict__ bn2_b,
    const float* __restrict__ bn2_m, const float* __restrict__ bn2_v,
    const float* __restrict__ conv3_w, const float* __restrict__ conv3_b,
    float* __restrict__ out)
{
    extern __shared__ float4 spts[];
    __shared__ float W1f[81], W2f[81], W3s[81];
    __shared__ float b1f[9], b2f[9], b3f[9];

    const int b  = blockIdx.x >> 4;
    const int n0 = (blockIdx.x & 15) * 256;
    const int tid = threadIdx.x;

    if (tid < 81) {
        int o = tid / 9;
        float i1 = bn1_g[o] * rsqrtf(bn1_v[o] + 1e-5f);
        float i2 = bn2_g[o] * rsqrtf(bn2_v[o] + 1e-5f);
        W1f[tid] = conv1_w[tid] * i1;
        W2f[tid] = conv2_w[tid] * i2;
        W3s[tid] = conv3_w[tid];
        if (tid < 9) {
            float j1 = bn1_g[tid] * rsqrtf(bn1_v[tid] + 1e-5f);
            float j2 = bn2_g[tid] * rsqrtf(bn2_v[tid] + 1e-5f);
            b1f[tid] = bn1_b[tid] - bn1_m[tid] * j1;
            b2f[tid] = conv2_b[tid] * j2 + bn2_b[tid] - bn2_m[tid] * j2;
            b3f[tid] = conv3_b[tid];
        }
    }

    const float* xb = x + b * 3 * NPTS;
    for (int i = tid; i < NPTS; i += blockDim.x) {
        spts[i] = make_float4(xb[i], xb[NPTS + i], xb[2 * NPTS + i], 0.0f);
    }
    __syncthreads();

    const int n = n0 + tid;
    float4 p = spts[n];

    float gx[NNB], gy[NNB], gz[NNB], ph[NNB];
    const int* nb = g_knn_idx + (b * NPTS + n) * NNB;
#pragma unroll
    for (int j = 0; j < NNB; ++j) {
        float4 pp = spts[nb[j]];
        gx[j] = pp.x - p.x;
        gy[j] = pp.y - p.y;
        gz[j] = pp.z - p.z;
        ph[j] = atan2f(gy[j], gx[j]);
    }

#pragma unroll 1
    for (int a = 1; a < NNB; ++a) {
        float kp = ph[a], kx = gx[a], ky = gy[a], kz = gz[a];
        int t = a - 1;
        while (t >= 0 && ph[t] > kp) {
            ph[t + 1] = ph[t]; gx[t + 1] = gx[t]; gy[t + 1] = gy[t]; gz[t + 1] = gz[t];
            --t;
        }
        ph[t + 1] = kp; gx[t + 1] = kx; gy[t + 1] = ky; gz[t + 1] = kz;
    }

    float acc[9];
#pragma unroll
    for (int o = 0; o < 9; ++o) acc[o] = 0.0f;

    float pos = 1.0f;

#pragma unroll 1
    for (int j = 0; j < NNB; ++j) {
        int jn = (j + 1 == NNB) ? 0 : j + 1;
        float sx = gx[j],  sy = gy[j],  sz = gz[j];
        float rx = gx[jn], ry = gy[jn], rz = gz[jn];

        float cxv = sy * rz - sz * ry;
        float cyv = sz * rx - sx * rz;
        float czv = sx * ry - sy * rx;
        float nrm = sqrtf(cxv * cxv + cyv * cyv + czv * czv);
        float inn = 1.0f / fmaxf(nrm, 1e-10f);
        float ux = cxv * inn, uy = cyv * inn, uz = czv * inn;
        if (j == 0) pos = (ux > 0.0f) ? 1.0f : -1.0f;
        float nx = ux * pos, ny = uy * pos, nz = uz * pos;
        nx = isnan(nx) ? 0.0f : nx;
        ny = isnan(ny) ? 0.0f : ny;
        nz = isnan(nz) ? 0.0f : nz;

        float ccx = (sx + rx) * (1.0f / 3.0f);
        float ccy = (sy + ry) * (1.0f / 3.0f);
        float ccz = (sz + rz) * (1.0f / 3.0f);
        float rho = sqrtf(ccx * ccx + ccy * ccy + ccz * ccz);
        float ct  = ccz / fmaxf(rho, 1e-8f);
        ct = fminf(fmaxf(ct, -1.0f), 1.0f);
        float th  = acosf(ct) * (1.0f / PI_F);
        float phc = atan2f(ccy, ccx) * (1.0f / (2.0f * PI_F)) + 0.5f;

        float f[9] = { ccx, ccy, ccz, rho, th, phc, nx, ny, nz };

        float h1v[9];
#pragma unroll
        for (int o = 0; o < 9; ++o) {
            float a = b1f[o];
#pragma unroll
            for (int c = 0; c < 9; ++c) a = fmaf(W1f[o * 9 + c], f[c], a);
            h1v[o] = fmaxf(a, 0.0f);
        }
        float h2v[9];
#pragma unroll
        for (int o = 0; o < 9; ++o) {
            float a = b2f[o];
#pragma unroll
            for (int c = 0; c < 9; ++c) a = fmaf(W2f[o * 9 + c], h1v[c], a);
            h2v[o] = fmaxf(a, 0.0f);
        }
#pragma unroll
        for (int o = 0; o < 9; ++o) {
            float a = b3f[o];
#pragma unroll
            for (int c = 0; c < 9; ++c) a = fmaf(W3s[o * 9 + c], h2v[c], a);
            acc[o] += a;
        }
    }

    float* ob = out + b * 9 * NPTS + n;
#pragma unroll
    for (int o = 0; o < 9; ++o) ob[o * NPTS] = acc[o];
}

// ---------------------------------------------------------------------------
extern "C" void kernel_launch(void* const* d_in, const int* in_sizes, int n_in,
                              void* d_out, int out_size)
{
    const float* x       = (const float*)d_in[0];
    const float* conv1_w = (const float*)d_in[1];
    const float* bn1_g   = (const float*)d_in[2];
    const float* bn1_b   = (const float*)d_in[3];
    const float* bn1_m   = (const float*)d_in[4];
    const float* bn1_v   = (const float*)d_in[5];
    const float* conv2_w = (const float*)d_in[6];
    const float* conv2_b = (const float*)d_in[7];
    const float* bn2_g   = (const float*)d_in[8];
    const float* bn2_b   = (const float*)d_in[9];
    const float* bn2_m   = (const float*)d_in[10];
    const float* bn2_v   = (const float*)d_in[11];
    const float* conv3_w = (const float*)d_in[12];
    const float* conv3_b = (const float*)d_in[13];
    float* out = (float*)d_out;

    const int smem_knn  = 82948 + 16 + 20480 + 20480;     // ~121 KB
    const int smem_feat = NPTS * (int)sizeof(float4);     // 64 KB
    cudaFuncSetAttribute(knn_kernel,  cudaFuncAttributeMaxDynamicSharedMemorySize, smem_knn);
    cudaFuncSetAttribute(feat_kernel, cudaFuncAttributeMaxDynamicSharedMemorySize, smem_feat);

    binsort_kernel<<<BATCH, 512>>>(x);
    knn_kernel<<<BATCH * (NPTS / 256), 512, smem_knn>>>();
    feat_kernel<<<BATCH * (NPTS / 256), 256, smem_feat>>>(
        x, conv1_w, bn1_g, bn1_b, bn1_m, bn1_v,
        conv2_w, conv2_b, bn2_g, bn2_b, bn2_m, bn2_v,
        conv3_w, conv3_b, out);
}

// round 10
// speedup vs baseline: 1.4716x; 1.3011x over previous
#include <cuda_runtime.h>
#include <math.h>
#include <float.h>

#define BATCH 8
#define NPTS  4096
#define KN    10
#define NNB   9
#define PI_F  3.14159265358979323846f
#define INF_F __int_as_float(0x7f800000)

// scratch: neighbor indices (B, N, 9)
__device__ int g_knn_idx[BATCH * NPTS * NNB];

// ---------------------------------------------------------------------------
// insert: unsorted top-10, replace (first) slot equal to running max.
// parallel prefix-OR first-match + FMNMX tree. (proven exact, rounds 3-9)
// ---------------------------------------------------------------------------
#define KNN_INSERT(e, c)                                                     \
    if ((e) < mx) {                                                          \
        bool m0 = (bd[0] == mx), m1 = (bd[1] == mx);                         \
        bool m2 = (bd[2] == mx), m3 = (bd[3] == mx);                         \
        bool m4 = (bd[4] == mx), m5 = (bd[5] == mx);                         \
        bool m6 = (bd[6] == mx), m7 = (bd[7] == mx);                         \
        bool m8 = (bd[8] == mx), m9 = (bd[9] == mx);                         \
        bool o01 = m0 | m1, o23 = m2 | m3, o45 = m4 | m5, o67 = m6 | m7;     \
        bool o03 = o01 | o23, o07 = o03 | o45 | o67;                         \
        if (m0)                      { bd[0] = (e); bi[0] = (c); }           \
        if (m1 & !m0)                { bd[1] = (e); bi[1] = (c); }           \
        if (m2 & !o01)               { bd[2] = (e); bi[2] = (c); }           \
        if (m3 & !(o01 | m2))        { bd[3] = (e); bi[3] = (c); }           \
        if (m4 & !o03)               { bd[4] = (e); bi[4] = (c); }           \
        if (m5 & !(o03 | m4))        { bd[5] = (e); bi[5] = (c); }           \
        if (m6 & !(o03 | o45))       { bd[6] = (e); bi[6] = (c); }           \
        if (m7 & !(o03 | o45 | m6))  { bd[7] = (e); bi[7] = (c); }           \
        if (m8 & !o07)               { bd[8] = (e); bi[8] = (c); }           \
        if (m9 & !(o07 | m8))        { bd[9] = (e); bi[9] = (c); }           \
        float x0 = fmaxf(bd[0], bd[1]);                                      \
        float x1 = fmaxf(bd[2], bd[3]);                                      \
        float x2 = fmaxf(bd[4], bd[5]);                                      \
        float x3 = fmaxf(bd[6], bd[7]);                                      \
        float x4 = fmaxf(bd[8], bd[9]);                                      \
        mx = fmaxf(fmaxf(fmaxf(x0, x1), fmaxf(x2, x3)), x4);                 \
    }

// predicated append to per-thread smem stack (no branch body worth a BSSY)
#define KNN_APPEND(e, c)                                                     \
    if ((e) < mx) {                                                          \
        sstk[cnt * 512 + tid] = make_float2((e), __int_as_float(c));         \
        ++cnt;                                                               \
    }

// drain this thread's stack through the exact insert
#define KNN_DRAIN()                                                          \
    {                                                                        \
        for (int j = 0; j < cnt; ++j) {                                      \
            float2 v = sstk[j * 512 + tid];                                  \
            float de = v.x;                                                  \
            int   dc = __float_as_int(v.y);                                  \
            KNN_INSERT(de, dc);                                              \
        }                                                                    \
        cnt = 0;                                                             \
    }

// ---------------------------------------------------------------------------
// Kernel 1: brute-force kNN. 2 threads per query (2048 candidates each),
// 512-thread blocks, branch-free main loop with predicated stack appends;
// warp-voted batched drains. Exact 2-way merge; drop self (= global min).
// ---------------------------------------------------------------------------
__global__ void __launch_bounds__(512) knn_kernel(const float* __restrict__ x)
{
    extern __shared__ char dsm[];
    float4* spt  = (float4*)dsm;                 // 64 KB: {x,y,z, 0.5|p|^2}
    float2* sstk = (float2*)(dsm + 65536);       // 32 KB: 8-deep per-thread stacks

    const int b  = blockIdx.x >> 4;              // 16 blocks per batch
    const int q0 = (blockIdx.x & 15) << 8;       // 256 queries per block
    const float* xb = x + b * 3 * NPTS;
    const int tid = threadIdx.x;

    for (int i = tid; i < NPTS; i += 512) {
        float px = xb[i];
        float py = xb[NPTS + i];
        float pz = xb[2 * NPTS + i];
        spt[i] = make_float4(px, py, pz, 0.5f * (px * px + py * py + pz * pz));
    }
    __syncthreads();

    const int sub = tid >> 8;        // warps 0-7: sub 0, warps 8-15: sub 1
    const int ql  = tid & 255;
    const int q   = q0 + ql;
    const int c0  = sub * (NPTS / 2);

    const float4 qp = spt[q];
    const float nqx = -qp.x, nqy = -qp.y, nqz = -qp.z;

    float bd[KN];
    int   bi[KN];
#pragma unroll
    for (int s = 0; s < KN; ++s) { bd[s] = INF_F; bi[s] = 0; }
    float mx = INF_F;
    int cnt = 0;

#pragma unroll 2
    for (int c = c0; c < c0 + NPTS / 2; c += 4) {
        float4 p0 = spt[c];
        float4 p1 = spt[c + 1];
        float4 p2 = spt[c + 2];
        float4 p3 = spt[c + 3];
        float e0 = fmaf(nqx, p0.x, fmaf(nqy, p0.y, fmaf(nqz, p0.z, p0.w)));
        float e1 = fmaf(nqx, p1.x, fmaf(nqy, p1.y, fmaf(nqz, p1.z, p1.w)));
        float e2 = fmaf(nqx, p2.x, fmaf(nqy, p2.y, fmaf(nqz, p2.z, p2.w)));
        float e3 = fmaf(nqx, p3.x, fmaf(nqy, p3.y, fmaf(nqz, p3.z, p3.w)));
        KNN_APPEND(e0, c);
        KNN_APPEND(e1, c + 1);
        KNN_APPEND(e2, c + 2);
        KNN_APPEND(e3, c + 3);
        if (__any_sync(0xffffffffu, cnt >= 4)) {
            KNN_DRAIN();
        }
    }
    KNN_DRAIN();

    // --- exact merge of the two partial lists (reuse point region) ---
    __syncthreads();
    float* pd = (float*)dsm;                    // 512*10 floats = 20 KB
    int*   pi = (int*)(pd + 512 * KN);          // 512*10 ints   = 20 KB

    const int base = (ql * 2 + sub) * KN;
#pragma unroll
    for (int s = 0; s < KN; ++s) { pd[base + s] = bd[s]; pi[base + s] = bi[s]; }
    __syncthreads();

    if (sub == 0) {
        const int ob = (ql * 2 + 1) * KN;
#pragma unroll
        for (int s = 0; s < KN; ++s) {
            float e = pd[ob + s];
            int   c = pi[ob + s];
            KNN_INSERT(e, c);
        }

        // self = strict global min; emit the other 9 (order arbitrary)
        float mn = bd[0]; int ms = 0;
#pragma unroll
        for (int s = 1; s < KN; ++s) {
            if (bd[s] < mn) { mn = bd[s]; ms = s; }
        }
        int* outp = g_knn_idx + (b * NPTS + q) * NNB;
        int k = 0;
#pragma unroll
        for (int s = 0; s < KN; ++s) {
            if (s != ms) { outp[k] = bi[s]; ++k; }
        }
    }
}

// ---------------------------------------------------------------------------
// Kernel 2: umbrella features + fused MLP (BN folded). One thread per (b,n).
// ---------------------------------------------------------------------------
__global__ void __launch_bounds__(256) feat_kernel(
    const float* __restrict__ x,
    const float* __restrict__ conv1_w,
    const float* __restrict__ bn1_g, const float* __restrict__ bn1_b,
    const float* __restrict__ bn1_m, const float* __restrict__ bn1_v,
    const float* __restrict__ conv2_w, const float* __restrict__ conv2_b,
    const float* __restrict__ bn2_g, const float* __restrict__ bn2_b,
    const float* __restrict__ bn2_m, const float* __restrict__ bn2_v,
    const float* __restrict__ conv3_w, const float* __restrict__ conv3_b,
    float* __restrict__ out)
{
    extern __shared__ float4 spts[];
    __shared__ float W1f[81], W2f[81], W3s[81];
    __shared__ float b1f[9], b2f[9], b3f[9];

    const int b  = blockIdx.x >> 4;
    const int n0 = (blockIdx.x & 15) * 256;
    const int tid = threadIdx.x;

    if (tid < 81) {
        int o = tid / 9;
        float i1 = bn1_g[o] * rsqrtf(bn1_v[o] + 1e-5f);
        float i2 = bn2_g[o] * rsqrtf(bn2_v[o] + 1e-5f);
        W1f[tid] = conv1_w[tid] * i1;
        W2f[tid] = conv2_w[tid] * i2;
        W3s[tid] = conv3_w[tid];
        if (tid < 9) {
            float j1 = bn1_g[tid] * rsqrtf(bn1_v[tid] + 1e-5f);
            float j2 = bn2_g[tid] * rsqrtf(bn2_v[tid] + 1e-5f);
            b1f[tid] = bn1_b[tid] - bn1_m[tid] * j1;
            b2f[tid] = conv2_b[tid] * j2 + bn2_b[tid] - bn2_m[tid] * j2;
            b3f[tid] = conv3_b[tid];
        }
    }

    const float* xb = x + b * 3 * NPTS;
    for (int i = tid; i < NPTS; i += blockDim.x) {
        spts[i] = make_float4(xb[i], xb[NPTS + i], xb[2 * NPTS + i], 0.0f);
    }
    __syncthreads();

    const int n = n0 + tid;
    float4 p = spts[n];

    float gx[NNB], gy[NNB], gz[NNB], ph[NNB];
    const int* nb = g_knn_idx + (b * NPTS + n) * NNB;
#pragma unroll
    for (int j = 0; j < NNB; ++j) {
        float4 pp = spts[nb[j]];
        gx[j] = pp.x - p.x;
        gy[j] = pp.y - p.y;
        gz[j] = pp.z - p.z;
        ph[j] = atan2f(gy[j], gx[j]);
    }

#pragma unroll 1
    for (int a = 1; a < NNB; ++a) {
        float kp = ph[a], kx = gx[a], ky = gy[a], kz = gz[a];
        int t = a - 1;
        while (t >= 0 && ph[t] > kp) {
            ph[t + 1] = ph[t]; gx[t + 1] = gx[t]; gy[t + 1] = gy[t]; gz[t + 1] = gz[t];
            --t;
        }
        ph[t + 1] = kp; gx[t + 1] = kx; gy[t + 1] = ky; gz[t + 1] = kz;
    }

    float acc[9];
#pragma unroll
    for (int o = 0; o < 9; ++o) acc[o] = 0.0f;

    float pos = 1.0f;

#pragma unroll 1
    for (int j = 0; j < NNB; ++j) {
        int jn = (j + 1 == NNB) ? 0 : j + 1;
        float sx = gx[j],  sy = gy[j],  sz = gz[j];
        float rx = gx[jn], ry = gy[jn], rz = gz[jn];

        float cxv = sy * rz - sz * ry;
        float cyv = sz * rx - sx * rz;
        float czv = sx * ry - sy * rx;
        float nrm = sqrtf(cxv * cxv + cyv * cyv + czv * czv);
        float inn = 1.0f / fmaxf(nrm, 1e-10f);
        float ux = cxv * inn, uy = cyv * inn, uz = czv * inn;
        if (j == 0) pos = (ux > 0.0f) ? 1.0f : -1.0f;
        float nx = ux * pos, ny = uy * pos, nz = uz * pos;
        nx = isnan(nx) ? 0.0f : nx;
        ny = isnan(ny) ? 0.0f : ny;
        nz = isnan(nz) ? 0.0f : nz;

        float ccx = (sx + rx) * (1.0f / 3.0f);
        float ccy = (sy + ry) * (1.0f / 3.0f);
        float ccz = (sz + rz) * (1.0f / 3.0f);
        float rho = sqrtf(ccx * ccx + ccy * ccy + ccz * ccz);
        float ct  = ccz / fmaxf(rho, 1e-8f);
        ct = fminf(fmaxf(ct, -1.0f), 1.0f);
        float th  = acosf(ct) * (1.0f / PI_F);
        float phc = atan2f(ccy, ccx) * (1.0f / (2.0f * PI_F)) + 0.5f;

        float f[9] = { ccx, ccy, ccz, rho, th, phc, nx, ny, nz };

        float h1v[9];
#pragma unroll
        for (int o = 0; o < 9; ++o) {
            float a = b1f[o];
#pragma unroll
            for (int c = 0; c < 9; ++c) a = fmaf(W1f[o * 9 + c], f[c], a);
            h1v[o] = fmaxf(a, 0.0f);
        }
        float h2v[9];
#pragma unroll
        for (int o = 0; o < 9; ++o) {
            float a = b2f[o];
#pragma unroll
            for (int c = 0; c < 9; ++c) a = fmaf(W2f[o * 9 + c], h1v[c], a);
            h2v[o] = fmaxf(a, 0.0f);
        }
#pragma unroll
        for (int o = 0; o < 9; ++o) {
            float a = b3f[o];
#pragma unroll
            for (int c = 0; c < 9; ++c) a = fmaf(W3s[o * 9 + c], h2v[c], a);
            acc[o] += a;
        }
    }

    float* ob = out + b * 9 * NPTS + n;
#pragma unroll
    for (int o = 0; o < 9; ++o) ob[o * NPTS] = acc[o];
}

// ---------------------------------------------------------------------------
extern "C" void kernel_launch(void* const* d_in, const int* in_sizes, int n_in,
                              void* d_out, int out_size)
{
    const float* x       = (const float*)d_in[0];
    const float* conv1_w = (const float*)d_in[1];
    const float* bn1_g   = (const float*)d_in[2];
    const float* bn1_b   = (const float*)d_in[3];
    const float* bn1_m   = (const float*)d_in[4];
    const float* bn1_v   = (const float*)d_in[5];
    const float* conv2_w = (const float*)d_in[6];
    const float* conv2_b = (const float*)d_in[7];
    const float* bn2_g   = (const float*)d_in[8];
    const float* bn2_b   = (const float*)d_in[9];
    const float* bn2_m   = (const float*)d_in[10];
    const float* bn2_v   = (const float*)d_in[11];
    const float* conv3_w = (const float*)d_in[12];
    const float* conv3_b = (const float*)d_in[13];
    float* out = (float*)d_out;

    const int smem_knn  = 65536 + 32768;              // 96 KB
    const int smem_feat = NPTS * (int)sizeof(float4); // 64 KB
    cudaFuncSetAttribute(knn_kernel,  cudaFuncAttributeMaxDynamicSharedMemorySize, smem_knn);
    cudaFuncSetAttribute(feat_kernel, cudaFuncAttributeMaxDynamicSharedMemorySize, smem_feat);

    knn_kernel<<<BATCH * (NPTS / 256), 512, smem_knn>>>(x);
    feat_kernel<<<BATCH * (NPTS / 256), 256, smem_feat>>>(
        x, conv1_w, bn1_g, bn1_b, bn1_m, bn1_v,
        conv2_w, conv2_b, bn2_g, bn2_b, bn2_m, bn2_v,
        conv3_w, conv3_b, out);
}